// round 1
// baseline (speedup 1.0000x reference)
#include <cuda_runtime.h>
#include <math.h>

// ---------------- problem constants ----------------
#define DMODEL 1024
#define NHEAD  16
#define DKH    64
#define RNK    256
#define BATCH  4
#define SEQ    2048
#define ROWS   (BATCH * SEQ)                 // 8192
static const long long OUT_ELEMS  = (long long)ROWS * DMODEL;            // 8,388,608
static const long long ATTN_ELEMS = (long long)BATCH * NHEAD * SEQ * SEQ; // 268,435,456

// ---------------- static scratch (no allocation allowed) ----------------
__device__ float g_tmp[ROWS * RNK];     // low-rank intermediate (reused q,k,v,fc)
__device__ float g_qh [ROWS * DMODEL];  // (B,S,H,Dk) flattened
__device__ float g_kh [ROWS * DMODEL];
__device__ float g_vh [ROWS * DMODEL];
__device__ float g_ctx[ROWS * DMODEL];
__device__ float g_pre[ROWS * DMODEL];  // pre-layernorm
__device__ float g_attn_scratch[(size_t)BATCH * NHEAD * SEQ * SEQ]; // used only if attn not in d_out

// ---------------- generic batched tiled SGEMM ----------------
// C[z] = alpha * A[z] (@ or @^T) B[z] (+ R)     all row-major, strided per z.
// per-z offset = (z/zc)*outerStride + (z%zc)*innerStride
template <int BM, int BN, int BK, int TM, int TN, bool TRANSB>
__global__ void gemm_kernel(const float* __restrict__ A, int lda, long long sAo, long long sAi,
                            const float* __restrict__ B, int ldb, long long sBo, long long sBi,
                            float* __restrict__ C, int ldc, long long sCo, long long sCi,
                            const float* __restrict__ R,
                            int M, int N, int K, float alpha, int zc)
{
    constexpr int THREADS = (BM / TM) * (BN / TN);
    __shared__ float As[BK][BM];
    __shared__ float Bs[BK][BN];

    const int z  = blockIdx.z;
    const int zo = z / zc, zi = z % zc;
    A += zo * sAo + zi * sAi;
    B += zo * sBo + zi * sBi;
    C += zo * sCo + zi * sCi;

    const int row0 = blockIdx.y * BM;
    const int col0 = blockIdx.x * BN;
    const int t  = threadIdx.x;
    const int tx = t % (BN / TN);
    const int ty = t / (BN / TN);

    float acc[TM][TN];
    #pragma unroll
    for (int i = 0; i < TM; i++)
        #pragma unroll
        for (int j = 0; j < TN; j++) acc[i][j] = 0.f;

    for (int k0 = 0; k0 < K; k0 += BK) {
        // A tile: BM x BK  ->  As[k][m]
        #pragma unroll 4
        for (int idx = t; idx < BM * BK; idx += THREADS) {
            int r = idx / BK, c = idx % BK;
            As[c][r] = A[(long long)(row0 + r) * lda + (k0 + c)];
        }
        if constexpr (TRANSB) {
            // B tile: BN x BK (B is N x K row-major) -> Bs[k][n]
            #pragma unroll 4
            for (int idx = t; idx < BN * BK; idx += THREADS) {
                int r = idx / BK, c = idx % BK;
                Bs[c][r] = B[(long long)(col0 + r) * ldb + (k0 + c)];
            }
        } else {
            // B tile: BK x BN (B is K x N row-major) -> Bs[k][n]
            #pragma unroll 4
            for (int idx = t; idx < BK * BN; idx += THREADS) {
                int r = idx / BN, c = idx % BN;
                Bs[r][c] = B[(long long)(k0 + r) * ldb + (col0 + c)];
            }
        }
        __syncthreads();

        #pragma unroll
        for (int k = 0; k < BK; k++) {
            float af[TM], bf[TN];
            #pragma unroll
            for (int i = 0; i < TM; i++) af[i] = As[k][ty * TM + i];
            #pragma unroll
            for (int j = 0; j < TN; j++) bf[j] = Bs[k][tx * TN + j];
            #pragma unroll
            for (int i = 0; i < TM; i++)
                #pragma unroll
                for (int j = 0; j < TN; j++)
                    acc[i][j] += af[i] * bf[j];
        }
        __syncthreads();
    }

    #pragma unroll
    for (int i = 0; i < TM; i++) {
        int r = row0 + ty * TM + i;
        #pragma unroll
        for (int j = 0; j < TN; j++) {
            int c = col0 + tx * TN + j;
            float v = acc[i][j] * alpha;
            if (R) v += R[(long long)r * ldc + c];
            C[(long long)r * ldc + c] = v;
        }
    }
}

// ---------------- softmax over rows of length 2048, in place ----------------
__global__ void softmax_rows_kernel(float* __restrict__ P)
{
    const int t = threadIdx.x;                       // 256 threads
    float* row = P + (long long)blockIdx.x * SEQ;

    float vals[8];
    float mx = -1e30f;
    #pragma unroll
    for (int i = 0; i < 8; i++) {
        vals[i] = row[t + i * 256];
        mx = fmaxf(mx, vals[i]);
    }
    __shared__ float redm[8];
    __shared__ float reds[8];
    #pragma unroll
    for (int o = 16; o; o >>= 1) mx = fmaxf(mx, __shfl_xor_sync(0xffffffffu, mx, o));
    if ((t & 31) == 0) redm[t >> 5] = mx;
    __syncthreads();
    float bmax = redm[0];
    #pragma unroll
    for (int w = 1; w < 8; w++) bmax = fmaxf(bmax, redm[w]);

    float s = 0.f;
    #pragma unroll
    for (int i = 0; i < 8; i++) {
        vals[i] = expf(vals[i] - bmax);
        s += vals[i];
    }
    #pragma unroll
    for (int o = 16; o; o >>= 1) s += __shfl_xor_sync(0xffffffffu, s, o);
    if ((t & 31) == 0) reds[t >> 5] = s;
    __syncthreads();
    float bsum = 0.f;
    #pragma unroll
    for (int w = 0; w < 8; w++) bsum += reds[w];

    const float inv = 1.f / bsum;
    #pragma unroll
    for (int i = 0; i < 8; i++) row[t + i * 256] = vals[i] * inv;
}

// ---------------- layernorm over rows of 1024 ----------------
__global__ void layernorm_kernel(const float* __restrict__ X,
                                 const float* __restrict__ gamma,
                                 const float* __restrict__ beta,
                                 float* __restrict__ O)
{
    const int t = threadIdx.x;                       // 256 threads
    const float* x = X + (long long)blockIdx.x * DMODEL;
    float* o = O + (long long)blockIdx.x * DMODEL;

    float v[4];
    float s = 0.f;
    #pragma unroll
    for (int i = 0; i < 4; i++) { v[i] = x[t + i * 256]; s += v[i]; }

    __shared__ float red1[8];
    __shared__ float red2[8];
    #pragma unroll
    for (int o2 = 16; o2; o2 >>= 1) s += __shfl_xor_sync(0xffffffffu, s, o2);
    if ((t & 31) == 0) red1[t >> 5] = s;
    __syncthreads();
    float tot = 0.f;
    #pragma unroll
    for (int w = 0; w < 8; w++) tot += red1[w];
    const float mean = tot * (1.f / DMODEL);

    float sq = 0.f;
    #pragma unroll
    for (int i = 0; i < 4; i++) { float d = v[i] - mean; sq += d * d; }
    #pragma unroll
    for (int o2 = 16; o2; o2 >>= 1) sq += __shfl_xor_sync(0xffffffffu, sq, o2);
    if ((t & 31) == 0) red2[t >> 5] = sq;
    __syncthreads();
    float vtot = 0.f;
    #pragma unroll
    for (int w = 0; w < 8; w++) vtot += red2[w];
    const float rstd = rsqrtf(vtot * (1.f / DMODEL) + 1e-6f);

    #pragma unroll
    for (int i = 0; i < 4; i++) {
        int c = t + i * 256;
        o[c] = (v[i] - mean) * rstd * gamma[c] + beta[c];
    }
}

// ---------------- host launch ----------------
extern "C" void kernel_launch(void* const* d_in, const int* in_sizes, int n_in,
                              void* d_out, int out_size)
{
    (void)in_sizes; (void)n_in;
    const float* q    = (const float*)d_in[0];
    const float* k    = (const float*)d_in[1];
    const float* v    = (const float*)d_in[2];
    const float* wqu  = (const float*)d_in[3];
    const float* wqv  = (const float*)d_in[4];
    const float* wku  = (const float*)d_in[5];
    const float* wkv  = (const float*)d_in[6];
    const float* wvu  = (const float*)d_in[7];
    const float* wvv  = (const float*)d_in[8];
    const float* fcu  = (const float*)d_in[9];
    const float* fcv  = (const float*)d_in[10];
    const float* lng  = (const float*)d_in[11];
    const float* lnb  = (const float*)d_in[12];
    float* out = (float*)d_out;

    float *p_tmp, *p_qh, *p_kh, *p_vh, *p_ctx, *p_pre, *p_scratch;
    cudaGetSymbolAddress((void**)&p_tmp, g_tmp);
    cudaGetSymbolAddress((void**)&p_qh,  g_qh);
    cudaGetSymbolAddress((void**)&p_kh,  g_kh);
    cudaGetSymbolAddress((void**)&p_vh,  g_vh);
    cudaGetSymbolAddress((void**)&p_ctx, g_ctx);
    cudaGetSymbolAddress((void**)&p_pre, g_pre);
    cudaGetSymbolAddress((void**)&p_scratch, g_attn_scratch);

    // attn buffer: part of output if the harness expects (out, attn) flattened
    float* attn = ((long long)out_size >= OUT_ELEMS + ATTN_ELEMS) ? (out + OUT_ELEMS)
                                                                  : p_scratch;

    const dim3 blk(256);
    const long long BH_A_OUT = (long long)SEQ * DMODEL; // per-batch stride into (B,S,H*Dk)
    const long long BH_A_IN  = DKH;                      // per-head column offset
    const long long ATT_S    = (long long)SEQ * SEQ;     // per-(b,h) attn stride

    // ---- low-rank projections: x @ Wu -> tmp ; tmp @ Wv -> head buffer ----
    struct Proj { const float* x; const float* wu; const float* wv; float* dst; };
    Proj pr[3] = { {q, wqu, wqv, p_qh}, {k, wku, wkv, p_kh}, {v, wvu, wvv, p_vh} };
    for (int i = 0; i < 3; i++) {
        gemm_kernel<128,128,8,8,8,false><<<dim3(RNK/128, ROWS/128, 1), blk>>>(
            pr[i].x, DMODEL, 0, 0,  pr[i].wu, RNK, 0, 0,
            p_tmp, RNK, 0, 0,  nullptr, ROWS, RNK, DMODEL, 1.f, 1);
        gemm_kernel<128,128,8,8,8,false><<<dim3(DMODEL/128, ROWS/128, 1), blk>>>(
            p_tmp, RNK, 0, 0,  pr[i].wv, DMODEL, 0, 0,
            pr[i].dst, DMODEL, 0, 0,  nullptr, ROWS, DMODEL, RNK, 1.f, 1);
    }

    // ---- scores: attn[b,h] = (1/8) * Qh @ Kh^T   (M=N=2048, K=64) ----
    gemm_kernel<128,128,8,8,8,true><<<dim3(SEQ/128, SEQ/128, BATCH*NHEAD), blk>>>(
        p_qh, DMODEL, BH_A_OUT, BH_A_IN,
        p_kh, DMODEL, BH_A_OUT, BH_A_IN,
        attn, SEQ, ATT_S * NHEAD, ATT_S,
        nullptr, SEQ, SEQ, DKH, 0.125f, NHEAD);

    // ---- softmax in place over all rows ----
    softmax_rows_kernel<<<(unsigned)(BATCH * NHEAD * SEQ), blk>>>(attn);

    // ---- ctx: ctx[b,h] = P @ Vh   (M=2048, N=64, K=2048) ----
    gemm_kernel<128,64,16,8,4,false><<<dim3(1, SEQ/128, BATCH*NHEAD), blk>>>(
        attn, SEQ, ATT_S * NHEAD, ATT_S,
        p_vh, DMODEL, BH_A_OUT, BH_A_IN,
        p_ctx, DMODEL, BH_A_OUT, BH_A_IN,
        nullptr, SEQ, DKH, SEQ, 1.f, NHEAD);

    // ---- fc: tmp = ctx @ fc_u ; pre = tmp @ fc_v + residual(q) ----
    gemm_kernel<128,128,8,8,8,false><<<dim3(RNK/128, ROWS/128, 1), blk>>>(
        p_ctx, DMODEL, 0, 0,  fcu, RNK, 0, 0,
        p_tmp, RNK, 0, 0,  nullptr, ROWS, RNK, DMODEL, 1.f, 1);
    gemm_kernel<128,128,8,8,8,false><<<dim3(DMODEL/128, ROWS/128, 1), blk>>>(
        p_tmp, RNK, 0, 0,  fcv, DMODEL, 0, 0,
        p_pre, DMODEL, 0, 0,  q, ROWS, DMODEL, RNK, 1.f, 1);

    // ---- layernorm -> out ----
    layernorm_kernel<<<ROWS, blk>>>(p_pre, lng, lnb, out);
}

// round 3
// speedup vs baseline: 3.7474x; 3.7474x over previous
#include <cuda_runtime.h>
#include <cstdint>
#include <math.h>

// ---------------- problem constants ----------------
#define DMODEL 1024
#define NHEAD  16
#define DKH    64
#define RNK    256
#define BATCH  4
#define SEQ    2048
#define ROWS   (BATCH * SEQ)                 // 8192
static const long long OUT_ELEMS  = (long long)ROWS * DMODEL;             // 8,388,608
static const long long ATTN_ELEMS = (long long)BATCH * NHEAD * SEQ * SEQ; // 268,435,456

// ---------------- static scratch ----------------
__device__ float g_tmp[ROWS * RNK];
__device__ float g_qh [ROWS * DMODEL];
__device__ float g_kh [ROWS * DMODEL];
__device__ float g_vh [ROWS * DMODEL];
__device__ float g_ctx[ROWS * DMODEL];
__device__ float g_pre[ROWS * DMODEL];
__device__ float g_attn_scratch[(size_t)BATCH * NHEAD * SEQ * SEQ];

// ---------------- PTX helpers ----------------
__device__ __forceinline__ uint32_t smem_u32(const void* p) {
    uint32_t a;
    asm("{ .reg .u64 t; cvta.to.shared.u64 t, %1; cvt.u32.u64 %0, t; }" : "=r"(a) : "l"(p));
    return a;
}
__device__ __forceinline__ uint32_t f2tf32(float x) {
    uint32_t r;
    asm("cvt.rna.tf32.f32 %0, %1;" : "=r"(r) : "f"(x));
    return r;
}
#define CP16(dst, src) \
    asm volatile("cp.async.cg.shared.global [%0], [%1], 16;" :: "r"(dst), "l"(src))
#define CP_COMMIT() asm volatile("cp.async.commit_group;")
#define CP_WAIT(N)  asm volatile("cp.async.wait_group %0;" :: "n"(N))

__device__ __forceinline__ void mma_tf32(float* c, const uint32_t* a, const uint32_t* b) {
    asm volatile("mma.sync.aligned.m16n8k8.row.col.f32.tf32.tf32.f32 "
                 "{%0,%1,%2,%3}, {%4,%5,%6,%7}, {%8,%9}, {%0,%1,%2,%3};"
                 : "+f"(c[0]), "+f"(c[1]), "+f"(c[2]), "+f"(c[3])
                 : "r"(a[0]), "r"(a[1]), "r"(a[2]), "r"(a[3]),
                   "r"(b[0]), "r"(b[1]));
}

// ---------------- tiled tf32 mma.sync GEMM ----------------
// C[z][M,N] = alpha * A[z][M,K] @ op(B[z]) (+ R)
// NMAJOR=true : B source is [K,N] row-major
// NMAJOR=false: B source is [N,K] row-major (i.e. C = A @ B^T)
// Tile: 128 x BN x 16, 8 warps, warp tile WM x WN.
template <int BN, int WM, int WN, bool NMAJOR, bool RES>
__global__ void __launch_bounds__(256)
gemm_mma(const float* __restrict__ A, int lda, long long sAo, long long sAi,
         const float* __restrict__ B, int ldb, long long sBo, long long sBi,
         float* __restrict__ C, int ldc, long long sCo, long long sCi,
         const float* __restrict__ R, int K, float alpha, int zc)
{
    constexpr int BM = 128;
    constexpr int BK = 16;
    constexpr int MT = WM / 16;
    constexpr int NT = WN / 8;
    constexpr int WCOLS = BN / WN;
    constexpr int ASTR = BK + 4;                    // 20 floats, 80B (16B mult)
    constexpr int BROWS = NMAJOR ? BK : BN;
    constexpr int BSTR  = NMAJOR ? (BN + 4) : (BK + 4);

    __shared__ float As[2][BM * ASTR];
    __shared__ float Bs[2][BROWS * BSTR];

    const int z  = blockIdx.z;
    const int zo = z / zc, zi = z % zc;
    A += zo * sAo + zi * sAi;
    B += zo * sBo + zi * sBi;
    C += zo * sCo + zi * sCi;
    if (RES) R += zo * sCo + zi * sCi;

    const int row0 = blockIdx.y * BM;
    const int col0 = blockIdx.x * BN;
    const int tid = threadIdx.x;
    const int wid = tid >> 5;
    const int lid = tid & 31;
    const int g = lid >> 2;                          // group id 0..7
    const int t = lid & 3;                           // thread-in-group
    const int wr = wid / WCOLS;                      // warp row
    const int wc = wid % WCOLS;                      // warp col
    const int wm0 = wr * WM;
    const int wn0 = wc * WN;

    const uint32_t sA0 = smem_u32(&As[0][0]);
    const uint32_t sA1 = smem_u32(&As[1][0]);
    const uint32_t sB0 = smem_u32(&Bs[0][0]);
    const uint32_t sB1 = smem_u32(&Bs[1][0]);

    float acc[MT][NT][4];
    #pragma unroll
    for (int i = 0; i < MT; i++)
        #pragma unroll
        for (int j = 0; j < NT; j++)
            #pragma unroll
            for (int x = 0; x < 4; x++) acc[i][j][x] = 0.f;

    const int KT = K >> 4;

    auto load_tile = [&](int kt, int buf) {
        const int k0 = kt * BK;
        const uint32_t sa = buf ? sA1 : sA0;
        const uint32_t sbm = buf ? sB1 : sB0;
        // A: BM rows x 16 floats = 512 x 16B segments
        #pragma unroll
        for (int i = 0; i < (BM * 4) / 256; i++) {
            int idx = tid + i * 256;
            int r = idx >> 2, s = idx & 3;
            CP16(sa + (uint32_t)(r * ASTR + s * 4) * 4,
                 A + (long long)(row0 + r) * lda + k0 + s * 4);
        }
        if constexpr (NMAJOR) {
            // B: 16 rows x BN floats
            #pragma unroll
            for (int i = 0; i < (BK * BN / 4) / 256; i++) {
                int idx = tid + i * 256;
                int r = idx / (BN / 4), s = idx % (BN / 4);
                CP16(sbm + (uint32_t)(r * BSTR + s * 4) * 4,
                     B + (long long)(k0 + r) * ldb + col0 + s * 4);
            }
        } else {
            // B: BN rows x 16 floats
            #pragma unroll
            for (int i = 0; i < (BN * 4) / 256; i++) {
                int idx = tid + i * 256;
                int r = idx >> 2, s = idx & 3;
                CP16(sbm + (uint32_t)(r * BSTR + s * 4) * 4,
                     B + (long long)(col0 + r) * ldb + k0 + s * 4);
            }
        }
        CP_COMMIT();
    };

    load_tile(0, 0);

    for (int kt = 0; kt < KT; kt++) {
        const int buf = kt & 1;
        if (kt + 1 < KT) {
            load_tile(kt + 1, buf ^ 1);
            CP_WAIT(1);
        } else {
            CP_WAIT(0);
        }
        __syncthreads();

        const float* pa = As[buf];
        const float* pb = Bs[buf];
        #pragma unroll
        for (int ks = 0; ks < 2; ks++) {
            uint32_t af[MT][4];
            uint32_t bf[NT][2];
            #pragma unroll
            for (int mi = 0; mi < MT; mi++) {
                int ar = wm0 + mi * 16 + g;
                int ac = ks * 8 + t;
                af[mi][0] = f2tf32(pa[ar * ASTR + ac]);
                af[mi][1] = f2tf32(pa[(ar + 8) * ASTR + ac]);
                af[mi][2] = f2tf32(pa[ar * ASTR + ac + 4]);
                af[mi][3] = f2tf32(pa[(ar + 8) * ASTR + ac + 4]);
            }
            #pragma unroll
            for (int ni = 0; ni < NT; ni++) {
                int bn = wn0 + ni * 8 + g;
                int bk = ks * 8 + t;
                if constexpr (NMAJOR) {
                    bf[ni][0] = f2tf32(pb[bk * BSTR + bn]);
                    bf[ni][1] = f2tf32(pb[(bk + 4) * BSTR + bn]);
                } else {
                    bf[ni][0] = f2tf32(pb[bn * BSTR + bk]);
                    bf[ni][1] = f2tf32(pb[bn * BSTR + bk + 4]);
                }
            }
            #pragma unroll
            for (int mi = 0; mi < MT; mi++)
                #pragma unroll
                for (int ni = 0; ni < NT; ni++)
                    mma_tf32(acc[mi][ni], af[mi], bf[ni]);
        }
        __syncthreads();
    }

    // ---- epilogue ----
    #pragma unroll
    for (int mi = 0; mi < MT; mi++) {
        #pragma unroll
        for (int ni = 0; ni < NT; ni++) {
            int r0 = row0 + wm0 + mi * 16 + g;
            int c0 = col0 + wn0 + ni * 8 + 2 * t;
            long long i0 = (long long)r0 * ldc + c0;
            long long i1 = i0 + 8LL * ldc;
            float v0 = acc[mi][ni][0] * alpha;
            float v1 = acc[mi][ni][1] * alpha;
            float v2 = acc[mi][ni][2] * alpha;
            float v3 = acc[mi][ni][3] * alpha;
            if constexpr (RES) {
                v0 += R[i0]; v1 += R[i0 + 1];
                v2 += R[i1]; v3 += R[i1 + 1];
            }
            *reinterpret_cast<float2*>(C + i0) = make_float2(v0, v1);
            *reinterpret_cast<float2*>(C + i1) = make_float2(v2, v3);
        }
    }
}

// ---------------- softmax over rows of length 2048, in place ----------------
__global__ void softmax_rows_kernel(float* __restrict__ P)
{
    const int t = threadIdx.x;                       // 256 threads
    float* row = P + (long long)blockIdx.x * SEQ;

    float vals[8];
    float mx = -1e30f;
    #pragma unroll
    for (int i = 0; i < 8; i++) { vals[i] = row[t + i * 256]; mx = fmaxf(mx, vals[i]); }
    __shared__ float redm[8];
    __shared__ float reds[8];
    #pragma unroll
    for (int o = 16; o; o >>= 1) mx = fmaxf(mx, __shfl_xor_sync(0xffffffffu, mx, o));
    if ((t & 31) == 0) redm[t >> 5] = mx;
    __syncthreads();
    float bmax = redm[0];
    #pragma unroll
    for (int w = 1; w < 8; w++) bmax = fmaxf(bmax, redm[w]);

    float s = 0.f;
    #pragma unroll
    for (int i = 0; i < 8; i++) { vals[i] = expf(vals[i] - bmax); s += vals[i]; }
    #pragma unroll
    for (int o = 16; o; o >>= 1) s += __shfl_xor_sync(0xffffffffu, s, o);
    if ((t & 31) == 0) reds[t >> 5] = s;
    __syncthreads();
    float bsum = 0.f;
    #pragma unroll
    for (int w = 0; w < 8; w++) bsum += reds[w];

    const float inv = 1.f / bsum;
    #pragma unroll
    for (int i = 0; i < 8; i++) row[t + i * 256] = vals[i] * inv;
}

// ---------------- layernorm over rows of 1024 ----------------
__global__ void layernorm_kernel(const float* __restrict__ X,
                                 const float* __restrict__ gamma,
                                 const float* __restrict__ beta,
                                 float* __restrict__ O)
{
    const int t = threadIdx.x;                       // 256 threads
    const float* x = X + (long long)blockIdx.x * DMODEL;
    float* o = O + (long long)blockIdx.x * DMODEL;

    float v[4];
    float s = 0.f;
    #pragma unroll
    for (int i = 0; i < 4; i++) { v[i] = x[t + i * 256]; s += v[i]; }

    __shared__ float red1[8];
    __shared__ float red2[8];
    #pragma unroll
    for (int o2 = 16; o2; o2 >>= 1) s += __shfl_xor_sync(0xffffffffu, s, o2);
    if ((t & 31) == 0) red1[t >> 5] = s;
    __syncthreads();
    float tot = 0.f;
    #pragma unroll
    for (int w = 0; w < 8; w++) tot += red1[w];
    const float mean = tot * (1.f / DMODEL);

    float sq = 0.f;
    #pragma unroll
    for (int i = 0; i < 4; i++) { float d = v[i] - mean; sq += d * d; }
    #pragma unroll
    for (int o2 = 16; o2; o2 >>= 1) sq += __shfl_xor_sync(0xffffffffu, sq, o2);
    if ((t & 31) == 0) red2[t >> 5] = sq;
    __syncthreads();
    float vtot = 0.f;
    #pragma unroll
    for (int w = 0; w < 8; w++) vtot += red2[w];
    const float rstd = rsqrtf(vtot * (1.f / DMODEL) + 1e-6f);

    #pragma unroll
    for (int i = 0; i < 4; i++) {
        int c = t + i * 256;
        o[c] = (v[i] - mean) * rstd * gamma[c] + beta[c];
    }
}

// ---------------- host launch ----------------
extern "C" void kernel_launch(void* const* d_in, const int* in_sizes, int n_in,
                              void* d_out, int out_size)
{
    (void)in_sizes; (void)n_in;
    const float* q    = (const float*)d_in[0];
    const float* k    = (const float*)d_in[1];
    const float* v    = (const float*)d_in[2];
    const float* wqu  = (const float*)d_in[3];
    const float* wqv  = (const float*)d_in[4];
    const float* wku  = (const float*)d_in[5];
    const float* wkv  = (const float*)d_in[6];
    const float* wvu  = (const float*)d_in[7];
    const float* wvv  = (const float*)d_in[8];
    const float* fcu  = (const float*)d_in[9];
    const float* fcv  = (const float*)d_in[10];
    const float* lng  = (const float*)d_in[11];
    const float* lnb  = (const float*)d_in[12];
    float* out = (float*)d_out;

    float *p_tmp, *p_qh, *p_kh, *p_vh, *p_ctx, *p_pre, *p_scratch;
    cudaGetSymbolAddress((void**)&p_tmp, g_tmp);
    cudaGetSymbolAddress((void**)&p_qh,  g_qh);
    cudaGetSymbolAddress((void**)&p_kh,  g_kh);
    cudaGetSymbolAddress((void**)&p_vh,  g_vh);
    cudaGetSymbolAddress((void**)&p_ctx, g_ctx);
    cudaGetSymbolAddress((void**)&p_pre, g_pre);
    cudaGetSymbolAddress((void**)&p_scratch, g_attn_scratch);

    float* attn = ((long long)out_size >= OUT_ELEMS + ATTN_ELEMS) ? (out + OUT_ELEMS)
                                                                  : p_scratch;

    const dim3 blk(256);
    const long long BH  = (long long)SEQ * DMODEL;    // per-batch stride of (B,S,H*Dk)
    const long long ATT = (long long)SEQ * SEQ;       // per-(b,h) attn stride

    // ---- projections: x @ Wu -> tmp ; tmp @ Wv -> head buffer ----
    struct Proj { const float* x; const float* wu; const float* wv; float* dst; };
    Proj pr[3] = { {q, wqu, wqv, p_qh}, {k, wku, wkv, p_kh}, {v, wvu, wvv, p_vh} };
    for (int i = 0; i < 3; i++) {
        gemm_mma<128, 64, 32, true, false><<<dim3(RNK / 128, ROWS / 128, 1), blk>>>(
            pr[i].x, DMODEL, 0, 0,  pr[i].wu, RNK, 0, 0,
            p_tmp, RNK, 0, 0,  nullptr, DMODEL, 1.f, 1);
        gemm_mma<128, 64, 32, true, false><<<dim3(DMODEL / 128, ROWS / 128, 1), blk>>>(
            p_tmp, RNK, 0, 0,  pr[i].wv, DMODEL, 0, 0,
            pr[i].dst, DMODEL, 0, 0,  nullptr, RNK, 1.f, 1);
    }

    // ---- scores: attn[b,h] = (1/8) * Qh @ Kh^T  (B is [N,K] K-major) ----
    gemm_mma<128, 64, 32, false, false><<<dim3(SEQ / 128, SEQ / 128, BATCH * NHEAD), blk>>>(
        p_qh, DMODEL, BH, DKH,
        p_kh, DMODEL, BH, DKH,
        attn, SEQ, ATT * NHEAD, ATT,
        nullptr, DKH, 0.125f, NHEAD);

    // ---- softmax ----
    softmax_rows_kernel<<<(unsigned)(BATCH * NHEAD * SEQ), blk>>>(attn);

    // ---- ctx: ctx[b,h] = P @ Vh  (B is [K,N]) ----
    gemm_mma<64, 32, 32, true, false><<<dim3(1, SEQ / 128, BATCH * NHEAD), blk>>>(
        attn, SEQ, ATT * NHEAD, ATT,
        p_vh, DMODEL, BH, DKH,
        p_ctx, DMODEL, BH, DKH,
        nullptr, SEQ, 1.f, NHEAD);

    // ---- fc: tmp = ctx @ fc_u ; pre = tmp @ fc_v + residual(q) ----
    gemm_mma<128, 64, 32, true, false><<<dim3(RNK / 128, ROWS / 128, 1), blk>>>(
        p_ctx, DMODEL, 0, 0,  fcu, RNK, 0, 0,
        p_tmp, RNK, 0, 0,  nullptr, DMODEL, 1.f, 1);
    gemm_mma<128, 64, 32, true, true><<<dim3(DMODEL / 128, ROWS / 128, 1), blk>>>(
        p_tmp, RNK, 0, 0,  fcv, DMODEL, 0, 0,
        p_pre, DMODEL, 0, 0,  q, RNK, 1.f, 1);

    // ---- layernorm -> out ----
    layernorm_kernel<<<ROWS, blk>>>(p_pre, lng, lnb, out);
}

// round 4
// speedup vs baseline: 3.7680x; 1.0055x over previous
#include <cuda_runtime.h>
#include <cstdint>
#include <math.h>

// ---------------- problem constants ----------------
#define DMODEL 1024
#define NHEAD  16
#define DKH    64
#define RNK    256
#define BATCH  4
#define SEQ    2048
#define ROWS   (BATCH * SEQ)                 // 8192
static const long long OUT_ELEMS  = (long long)ROWS * DMODEL;             // 8,388,608
static const long long ATTN_ELEMS = (long long)BATCH * NHEAD * SEQ * SEQ; // 268,435,456

// ---------------- static scratch ----------------
__device__ float g_tmp[ROWS * RNK];
__device__ float g_qh [ROWS * DMODEL];
__device__ float g_kh [ROWS * DMODEL];
__device__ float g_vh [ROWS * DMODEL];
__device__ float g_ctx[ROWS * DMODEL];
__device__ float g_pre[ROWS * DMODEL];
__device__ float g_attn_scratch[(size_t)BATCH * NHEAD * SEQ * SEQ];

// ---------------- PTX helpers ----------------
__device__ __forceinline__ uint32_t smem_u32(const void* p) {
    uint32_t a;
    asm("{ .reg .u64 t; cvta.to.shared.u64 t, %1; cvt.u32.u64 %0, t; }" : "=r"(a) : "l"(p));
    return a;
}
__device__ __forceinline__ uint32_t f2tf32(float x) {
    uint32_t r;
    asm("cvt.rna.tf32.f32 %0, %1;" : "=r"(r) : "f"(x));
    return r;
}
#define CP16(dst, src) \
    asm volatile("cp.async.cg.shared.global [%0], [%1], 16;" :: "r"(dst), "l"(src))
#define CP_COMMIT() asm volatile("cp.async.commit_group;")
#define CP_WAIT(N)  asm volatile("cp.async.wait_group %0;" :: "n"(N))

__device__ __forceinline__ void mma_tf32(float* c, const uint32_t* a, const uint32_t* b) {
    asm volatile("mma.sync.aligned.m16n8k8.row.col.f32.tf32.tf32.f32 "
                 "{%0,%1,%2,%3}, {%4,%5,%6,%7}, {%8,%9}, {%0,%1,%2,%3};"
                 : "+f"(c[0]), "+f"(c[1]), "+f"(c[2]), "+f"(c[3])
                 : "r"(a[0]), "r"(a[1]), "r"(a[2]), "r"(a[3]),
                   "r"(b[0]), "r"(b[1]));
}

// ---------------- tiled tf32 mma.sync GEMM ----------------
// C[z][M,N] = alpha * A[z][M,K] @ op(B[z]) (+ R)
// NMAJOR=true : B source is [K,N] row-major
// NMAJOR=false: B source is [N,K] row-major (i.e. C = A @ B^T)
// Tile: 128 x BN x 16, 8 warps, warp tile WM x WN.
template <int BN, int WM, int WN, bool NMAJOR, bool RES>
__global__ void __launch_bounds__(256)
gemm_mma(const float* __restrict__ A, int lda, long long sAo, long long sAi,
         const float* __restrict__ B, int ldb, long long sBo, long long sBi,
         float* __restrict__ C, int ldc, long long sCo, long long sCi,
         const float* __restrict__ R, int K, float alpha, int zc)
{
    constexpr int BM = 128;
    constexpr int BK = 16;
    constexpr int MT = WM / 16;
    constexpr int NT = WN / 8;
    constexpr int WCOLS = BN / WN;
    constexpr int ASTR = BK + 4;                    // 20 floats, 80B (16B mult)
    constexpr int BROWS = NMAJOR ? BK : BN;
    constexpr int BSTR  = NMAJOR ? (BN + 4) : (BK + 4);

    __shared__ float As[2][BM * ASTR];
    __shared__ float Bs[2][BROWS * BSTR];

    const int z  = blockIdx.z;
    const int zo = z / zc, zi = z % zc;
    A += zo * sAo + zi * sAi;
    B += zo * sBo + zi * sBi;
    C += zo * sCo + zi * sCi;
    if (RES) R += zo * sCo + zi * sCi;

    const int row0 = blockIdx.y * BM;
    const int col0 = blockIdx.x * BN;
    const int tid = threadIdx.x;
    const int wid = tid >> 5;
    const int lid = tid & 31;
    const int g = lid >> 2;                          // group id 0..7
    const int t = lid & 3;                           // thread-in-group
    const int wr = wid / WCOLS;                      // warp row
    const int wc = wid % WCOLS;                      // warp col
    const int wm0 = wr * WM;
    const int wn0 = wc * WN;

    const uint32_t sA0 = smem_u32(&As[0][0]);
    const uint32_t sA1 = smem_u32(&As[1][0]);
    const uint32_t sB0 = smem_u32(&Bs[0][0]);
    const uint32_t sB1 = smem_u32(&Bs[1][0]);

    float acc[MT][NT][4];
    #pragma unroll
    for (int i = 0; i < MT; i++)
        #pragma unroll
        for (int j = 0; j < NT; j++)
            #pragma unroll
            for (int x = 0; x < 4; x++) acc[i][j][x] = 0.f;

    const int KT = K >> 4;

    auto load_tile = [&](int kt, int buf) {
        const int k0 = kt * BK;
        const uint32_t sa = buf ? sA1 : sA0;
        const uint32_t sbm = buf ? sB1 : sB0;
        // A: BM rows x 16 floats = 512 x 16B segments
        #pragma unroll
        for (int i = 0; i < (BM * 4) / 256; i++) {
            int idx = tid + i * 256;
            int r = idx >> 2, s = idx & 3;
            CP16(sa + (uint32_t)(r * ASTR + s * 4) * 4,
                 A + (long long)(row0 + r) * lda + k0 + s * 4);
        }
        if constexpr (NMAJOR) {
            // B: 16 rows x BN floats
            #pragma unroll
            for (int i = 0; i < (BK * BN / 4) / 256; i++) {
                int idx = tid + i * 256;
                int r = idx / (BN / 4), s = idx % (BN / 4);
                CP16(sbm + (uint32_t)(r * BSTR + s * 4) * 4,
                     B + (long long)(k0 + r) * ldb + col0 + s * 4);
            }
        } else {
            // B: BN rows x 16 floats
            #pragma unroll
            for (int i = 0; i < (BN * 4) / 256; i++) {
                int idx = tid + i * 256;
                int r = idx >> 2, s = idx & 3;
                CP16(sbm + (uint32_t)(r * BSTR + s * 4) * 4,
                     B + (long long)(col0 + r) * ldb + k0 + s * 4);
            }
        }
        CP_COMMIT();
    };

    load_tile(0, 0);

    for (int kt = 0; kt < KT; kt++) {
        const int buf = kt & 1;
        if (kt + 1 < KT) {
            load_tile(kt + 1, buf ^ 1);
            CP_WAIT(1);
        } else {
            CP_WAIT(0);
        }
        __syncthreads();

        const float* pa = As[buf];
        const float* pb = Bs[buf];
        #pragma unroll
        for (int ks = 0; ks < 2; ks++) {
            uint32_t af[MT][4];
            uint32_t bf[NT][2];
            #pragma unroll
            for (int mi = 0; mi < MT; mi++) {
                int ar = wm0 + mi * 16 + g;
                int ac = ks * 8 + t;
                af[mi][0] = f2tf32(pa[ar * ASTR + ac]);
                af[mi][1] = f2tf32(pa[(ar + 8) * ASTR + ac]);
                af[mi][2] = f2tf32(pa[ar * ASTR + ac + 4]);
                af[mi][3] = f2tf32(pa[(ar + 8) * ASTR + ac + 4]);
            }
            #pragma unroll
            for (int ni = 0; ni < NT; ni++) {
                int bn = wn0 + ni * 8 + g;
                int bk = ks * 8 + t;
                if constexpr (NMAJOR) {
                    bf[ni][0] = f2tf32(pb[bk * BSTR + bn]);
                    bf[ni][1] = f2tf32(pb[(bk + 4) * BSTR + bn]);
                } else {
                    bf[ni][0] = f2tf32(pb[bn * BSTR + bk]);
                    bf[ni][1] = f2tf32(pb[bn * BSTR + bk + 4]);
                }
            }
            #pragma unroll
            for (int mi = 0; mi < MT; mi++)
                #pragma unroll
                for (int ni = 0; ni < NT; ni++)
                    mma_tf32(acc[mi][ni], af[mi], bf[ni]);
        }
        __syncthreads();
    }

    // ---- epilogue ----
    #pragma unroll
    for (int mi = 0; mi < MT; mi++) {
        #pragma unroll
        for (int ni = 0; ni < NT; ni++) {
            int r0 = row0 + wm0 + mi * 16 + g;
            int c0 = col0 + wn0 + ni * 8 + 2 * t;
            long long i0 = (long long)r0 * ldc + c0;
            long long i1 = i0 + 8LL * ldc;
            float v0 = acc[mi][ni][0] * alpha;
            float v1 = acc[mi][ni][1] * alpha;
            float v2 = acc[mi][ni][2] * alpha;
            float v3 = acc[mi][ni][3] * alpha;
            if constexpr (RES) {
                v0 += R[i0]; v1 += R[i0 + 1];
                v2 += R[i1]; v3 += R[i1 + 1];
            }
            *reinterpret_cast<float2*>(C + i0) = make_float2(v0, v1);
            *reinterpret_cast<float2*>(C + i1) = make_float2(v2, v3);
        }
    }
}

// ---------------- softmax over rows of length 2048, in place ----------------
__global__ void softmax_rows_kernel(float* __restrict__ P)
{
    const int t = threadIdx.x;                       // 256 threads
    float* row = P + (long long)blockIdx.x * SEQ;

    float vals[8];
    float mx = -1e30f;
    #pragma unroll
    for (int i = 0; i < 8; i++) { vals[i] = row[t + i * 256]; mx = fmaxf(mx, vals[i]); }
    __shared__ float redm[8];
    __shared__ float reds[8];
    #pragma unroll
    for (int o = 16; o; o >>= 1) mx = fmaxf(mx, __shfl_xor_sync(0xffffffffu, mx, o));
    if ((t & 31) == 0) redm[t >> 5] = mx;
    __syncthreads();
    float bmax = redm[0];
    #pragma unroll
    for (int w = 1; w < 8; w++) bmax = fmaxf(bmax, redm[w]);

    float s = 0.f;
    #pragma unroll
    for (int i = 0; i < 8; i++) { vals[i] = expf(vals[i] - bmax); s += vals[i]; }
    #pragma unroll
    for (int o = 16; o; o >>= 1) s += __shfl_xor_sync(0xffffffffu, s, o);
    if ((t & 31) == 0) reds[t >> 5] = s;
    __syncthreads();
    float bsum = 0.f;
    #pragma unroll
    for (int w = 0; w < 8; w++) bsum += reds[w];

    const float inv = 1.f / bsum;
    #pragma unroll
    for (int i = 0; i < 8; i++) row[t + i * 256] = vals[i] * inv;
}

// ---------------- layernorm over rows of 1024 ----------------
__global__ void layernorm_kernel(const float* __restrict__ X,
                                 const float* __restrict__ gamma,
                                 const float* __restrict__ beta,
                                 float* __restrict__ O)
{
    const int t = threadIdx.x;                       // 256 threads
    const float* x = X + (long long)blockIdx.x * DMODEL;
    float* o = O + (long long)blockIdx.x * DMODEL;

    float v[4];
    float s = 0.f;
    #pragma unroll
    for (int i = 0; i < 4; i++) { v[i] = x[t + i * 256]; s += v[i]; }

    __shared__ float red1[8];
    __shared__ float red2[8];
    #pragma unroll
    for (int o2 = 16; o2; o2 >>= 1) s += __shfl_xor_sync(0xffffffffu, s, o2);
    if ((t & 31) == 0) red1[t >> 5] = s;
    __syncthreads();
    float tot = 0.f;
    #pragma unroll
    for (int w = 0; w < 8; w++) tot += red1[w];
    const float mean = tot * (1.f / DMODEL);

    float sq = 0.f;
    #pragma unroll
    for (int i = 0; i < 4; i++) { float d = v[i] - mean; sq += d * d; }
    #pragma unroll
    for (int o2 = 16; o2; o2 >>= 1) sq += __shfl_xor_sync(0xffffffffu, sq, o2);
    if ((t & 31) == 0) red2[t >> 5] = sq;
    __syncthreads();
    float vtot = 0.f;
    #pragma unroll
    for (int w = 0; w < 8; w++) vtot += red2[w];
    const float rstd = rsqrtf(vtot * (1.f / DMODEL) + 1e-6f);

    #pragma unroll
    for (int i = 0; i < 4; i++) {
        int c = t + i * 256;
        o[c] = (v[i] - mean) * rstd * gamma[c] + beta[c];
    }
}

// ---------------- host launch ----------------
extern "C" void kernel_launch(void* const* d_in, const int* in_sizes, int n_in,
                              void* d_out, int out_size)
{
    (void)in_sizes; (void)n_in;
    const float* q    = (const float*)d_in[0];
    const float* k    = (const float*)d_in[1];
    const float* v    = (const float*)d_in[2];
    const float* wqu  = (const float*)d_in[3];
    const float* wqv  = (const float*)d_in[4];
    const float* wku  = (const float*)d_in[5];
    const float* wkv  = (const float*)d_in[6];
    const float* wvu  = (const float*)d_in[7];
    const float* wvv  = (const float*)d_in[8];
    const float* fcu  = (const float*)d_in[9];
    const float* fcv  = (const float*)d_in[10];
    const float* lng  = (const float*)d_in[11];
    const float* lnb  = (const float*)d_in[12];
    float* out = (float*)d_out;

    float *p_tmp, *p_qh, *p_kh, *p_vh, *p_ctx, *p_pre, *p_scratch;
    cudaGetSymbolAddress((void**)&p_tmp, g_tmp);
    cudaGetSymbolAddress((void**)&p_qh,  g_qh);
    cudaGetSymbolAddress((void**)&p_kh,  g_kh);
    cudaGetSymbolAddress((void**)&p_vh,  g_vh);
    cudaGetSymbolAddress((void**)&p_ctx, g_ctx);
    cudaGetSymbolAddress((void**)&p_pre, g_pre);
    cudaGetSymbolAddress((void**)&p_scratch, g_attn_scratch);

    float* attn = ((long long)out_size >= OUT_ELEMS + ATTN_ELEMS) ? (out + OUT_ELEMS)
                                                                  : p_scratch;

    const dim3 blk(256);
    const long long BH  = (long long)SEQ * DMODEL;    // per-batch stride of (B,S,H*Dk)
    const long long ATT = (long long)SEQ * SEQ;       // per-(b,h) attn stride

    // ---- projections: x @ Wu -> tmp ; tmp @ Wv -> head buffer ----
    struct Proj { const float* x; const float* wu; const float* wv; float* dst; };
    Proj pr[3] = { {q, wqu, wqv, p_qh}, {k, wku, wkv, p_kh}, {v, wvu, wvv, p_vh} };
    for (int i = 0; i < 3; i++) {
        gemm_mma<128, 64, 32, true, false><<<dim3(RNK / 128, ROWS / 128, 1), blk>>>(
            pr[i].x, DMODEL, 0, 0,  pr[i].wu, RNK, 0, 0,
            p_tmp, RNK, 0, 0,  nullptr, DMODEL, 1.f, 1);
        gemm_mma<128, 64, 32, true, false><<<dim3(DMODEL / 128, ROWS / 128, 1), blk>>>(
            p_tmp, RNK, 0, 0,  pr[i].wv, DMODEL, 0, 0,
            pr[i].dst, DMODEL, 0, 0,  nullptr, RNK, 1.f, 1);
    }

    // ---- scores: attn[b,h] = (1/8) * Qh @ Kh^T  (B is [N,K] K-major) ----
    gemm_mma<128, 64, 32, false, false><<<dim3(SEQ / 128, SEQ / 128, BATCH * NHEAD), blk>>>(
        p_qh, DMODEL, BH, DKH,
        p_kh, DMODEL, BH, DKH,
        attn, SEQ, ATT * NHEAD, ATT,
        nullptr, DKH, 0.125f, NHEAD);

    // ---- softmax ----
    softmax_rows_kernel<<<(unsigned)(BATCH * NHEAD * SEQ), blk>>>(attn);

    // ---- ctx: ctx[b,h] = P @ Vh  (B is [K,N]) ----
    gemm_mma<64, 32, 32, true, false><<<dim3(1, SEQ / 128, BATCH * NHEAD), blk>>>(
        attn, SEQ, ATT * NHEAD, ATT,
        p_vh, DMODEL, BH, DKH,
        p_ctx, DMODEL, BH, DKH,
        nullptr, SEQ, 1.f, NHEAD);

    // ---- fc: tmp = ctx @ fc_u ; pre = tmp @ fc_v + residual(q) ----
    gemm_mma<128, 64, 32, true, false><<<dim3(RNK / 128, ROWS / 128, 1), blk>>>(
        p_ctx, DMODEL, 0, 0,  fcu, RNK, 0, 0,
        p_tmp, RNK, 0, 0,  nullptr, DMODEL, 1.f, 1);
    gemm_mma<128, 64, 32, true, true><<<dim3(DMODEL / 128, ROWS / 128, 1), blk>>>(
        p_tmp, RNK, 0, 0,  fcv, DMODEL, 0, 0,
        p_pre, DMODEL, 0, 0,  q, RNK, 1.f, 1);

    // ---- layernorm -> out ----
    layernorm_kernel<<<ROWS, blk>>>(p_pre, lng, lnb, out);
}